// round 3
// baseline (speedup 1.0000x reference)
#include <cuda_runtime.h>
#include <math.h>

// RotationPerturbationLayer: the reference's dense [B,N,N] tent-weight matmul
// is mathematically exact bilinear resampling (tent support = 2 per axis),
// with zero contribution outside [0, W-1] x [0, H-1]. We compute the 4-tap
// gather directly: O(B*C*N) instead of O(B*C*N^2).

#define RP_H 80
#define RP_W 80
#define RP_C 3
#define RP_B 4
#define RP_N (RP_H * RP_W)

__global__ void __launch_bounds__(256)
rotation_bilinear_kernel(const float* __restrict__ theta,
                         const float* __restrict__ image,
                         float* __restrict__ out)
{
    const int idx = blockIdx.x * blockDim.x + threadIdx.x;  // [0, B*N)
    if (idx >= RP_B * RP_N) return;

    const int b = idx / RP_N;
    const int n = idx - b * RP_N;
    const int gy = n / RP_W;
    const int gx = n - gy * RP_W;

    const float cx = (RP_W - 1) * 0.5f;
    const float cy = (RP_H - 1) * 0.5f;

    // degrees -> radians
    const float th = theta[b] * 0.017453292519943295f;
    float s, c;
    sincosf(th, &s, &c);

    const float xr = (float)gx - cx;
    const float yr = (float)gy - cy;
    // rotation [[cos, sin], [-sin, cos]]
    const float sx = fmaf(c, xr, fmaf(s, yr, cx));
    const float sy = fmaf(-s, xr, fmaf(c, yr, cy));

    const int x0 = (int)floorf(sx);
    const int y0 = (int)floorf(sy);
    const float fx = sx - (float)x0;
    const float fy = sy - (float)y0;
    const int x1 = x0 + 1;
    const int y1 = y0 + 1;

    // tap weights, zeroed when the tap falls outside the image (zero-fill)
    const bool vx0 = (x0 >= 0) && (x0 < RP_W);
    const bool vx1 = (x1 >= 0) && (x1 < RP_W);
    const bool vy0 = (y0 >= 0) && (y0 < RP_H);
    const bool vy1 = (y1 >= 0) && (y1 < RP_H);

    const float wx0 = vx0 ? (1.0f - fx) : 0.0f;
    const float wx1 = vx1 ? fx          : 0.0f;
    const float wy0 = vy0 ? (1.0f - fy) : 0.0f;
    const float wy1 = vy1 ? fy          : 0.0f;

    const float w00 = wy0 * wx0;
    const float w01 = wy0 * wx1;
    const float w10 = wy1 * wx0;
    const float w11 = wy1 * wx1;

    // clamped indices so loads are always in-bounds (weight is 0 when clamped)
    const int cx0 = min(max(x0, 0), RP_W - 1);
    const int cx1 = min(max(x1, 0), RP_W - 1);
    const int cy0 = min(max(y0, 0), RP_H - 1);
    const int cy1 = min(max(y1, 0), RP_H - 1);

    const int o00 = cy0 * RP_W + cx0;
    const int o01 = cy0 * RP_W + cx1;
    const int o10 = cy1 * RP_W + cx0;
    const int o11 = cy1 * RP_W + cx1;

    #pragma unroll
    for (int ch = 0; ch < RP_C; ch++) {
        const float* img = image + ch * RP_N;
        float v = w00 * __ldg(img + o00);
        v = fmaf(w01, __ldg(img + o01), v);
        v = fmaf(w10, __ldg(img + o10), v);
        v = fmaf(w11, __ldg(img + o11), v);
        out[(b * RP_C + ch) * RP_N + n] = v;
    }
}

extern "C" void kernel_launch(void* const* d_in, const int* in_sizes, int n_in,
                              void* d_out, int out_size)
{
    const float* theta = (const float*)d_in[0];  // [4]
    const float* image = (const float*)d_in[1];  // [3,80,80]
    float* out = (float*)d_out;                  // [4,3,80,80]

    const int total = RP_B * RP_N;  // 25600 threads
    const int block = 256;
    const int grid = (total + block - 1) / block;  // 100 blocks
    rotation_bilinear_kernel<<<grid, block>>>(theta, image, out);
}